// round 3
// baseline (speedup 1.0000x reference)
#include <cuda_runtime.h>

typedef unsigned long long ull;

#define DHW0 (128*128*128)
#define DHW1 (64*64*64)

// Scratch (device globals: allocation-free rule). ~345MB total.
__device__ float g_h0[(size_t)DHW0*16];   // conv0a out; later reused as conv1b out
__device__ float g_h1[(size_t)DHW0*16];   // conv0b out
__device__ float g_g0[(size_t)DHW1*32];   // convd0 out
__device__ float g_g1[(size_t)DHW1*32];   // conv1a out
__device__ int   g_m1[DHW1];
__device__ int   g_active[DHW0];
__device__ int   g_blockcnt[8192];
__device__ int   g_blockoff[8192];
__device__ int   g_cnt;

// ---- packed f32x2 helpers (Blackwell FFMA2 path) ----
__device__ __forceinline__ ull pack2(float a){
    ull r; asm("mov.b64 %0, {%1, %1};" : "=l"(r) : "f"(a)); return r;
}
__device__ __forceinline__ void ffma2(ull& c, ull a, ull b){
    asm("fma.rn.f32x2 %0, %1, %2, %0;" : "+l"(c) : "l"(a), "l"(b));
}
__device__ __forceinline__ float2 unpack2(ull v){
    float2 f; asm("mov.b64 {%0, %1}, %2;" : "=f"(f.x), "=f"(f.y) : "l"(v)); return f;
}

// ============================================================
// Active-voxel compaction (deterministic, no contended atomics)
// ============================================================
__global__ void count_kernel(const int* __restrict__ m0){
    int v = blockIdx.x*256 + threadIdx.x;
    int act = m0[v] ? 1 : 0;
    int c = __syncthreads_count(act);
    if (threadIdx.x == 0) g_blockcnt[blockIdx.x] = c;
}

__global__ void scan_kernel(){
    __shared__ int ssum[1024];
    int tid = threadIdx.x;
    int local[8]; int s = 0;
    #pragma unroll
    for (int k = 0; k < 8; k++){ local[k] = s; s += g_blockcnt[tid*8 + k]; }
    ssum[tid] = s; __syncthreads();
    for (int off = 1; off < 1024; off <<= 1){
        int val = (tid >= off) ? ssum[tid - off] : 0;
        __syncthreads();
        ssum[tid] += val;
        __syncthreads();
    }
    int base = (tid == 0) ? 0 : ssum[tid - 1];
    #pragma unroll
    for (int k = 0; k < 8; k++) g_blockoff[tid*8 + k] = base + local[k];
    if (tid == 1023) g_cnt = ssum[1023];
}

__global__ void scatter_kernel(const int* __restrict__ m0){
    __shared__ int warpoff[8];
    int v = blockIdx.x*256 + threadIdx.x;
    int act = m0[v] ? 1 : 0;
    unsigned b = __ballot_sync(0xffffffffu, act);
    int lane = threadIdx.x & 31, wid = threadIdx.x >> 5;
    if (lane == 0) warpoff[wid] = __popc(b);
    __syncthreads();
    if (threadIdx.x == 0){
        int s = 0;
        #pragma unroll
        for (int k = 0; k < 8; k++){ int t = warpoff[k]; warpoff[k] = s; s += t; }
    }
    __syncthreads();
    if (act){
        int rank = warpoff[wid] + __popc(b & ((1u << lane) - 1u));
        g_active[g_blockoff[blockIdx.x] + rank] = v;
    }
}

// ============================================================
// m1 = maxpool3d(m0, 3, stride 2, pad 1)
// ============================================================
__global__ void m1_kernel(const int* __restrict__ m0){
    int v = blockIdx.x*256 + threadIdx.x;
    if (v >= DHW1) return;
    int x = v & 63, y = (v >> 6) & 63, z = v >> 12;
    int mv = 0;
    for (int dz = 0; dz < 3; dz++){
        int iz = 2*z + dz - 1; if ((unsigned)iz >= 128u) continue;
        for (int dy = 0; dy < 3; dy++){
            int iy = 2*y + dy - 1; if ((unsigned)iy >= 128u) continue;
            for (int dx = 0; dx < 3; dx++){
                int ix = 2*x + dx - 1; if ((unsigned)ix >= 128u) continue;
                mv |= m0[(iz << 14) | (iy << 7) | ix];
            }
        }
    }
    g_m1[v] = mv;
}

// ============================================================
// conv0a: 3 -> 16 @128^3, sparse (compacted outputs, m0 tap skip)
// ============================================================
__global__ void conv0a_kernel(const float* __restrict__ xf, const int* __restrict__ m0,
                              const float* __restrict__ w, const float* __restrict__ scale,
                              const float* __restrict__ shift){
    extern __shared__ float ws[];                 // [27][3][16]
    for (int e = threadIdx.x; e < 27*3*16; e += blockDim.x){
        int o = e & 15, i = (e >> 4) % 3, t = e / 48;
        ws[e] = w[(o*3 + i)*27 + t];
    }
    __syncthreads();
    int cnt = g_cnt;
    for (int idx = blockIdx.x*blockDim.x + threadIdx.x; idx < cnt;
         idx += gridDim.x*blockDim.x){
        int v = g_active[idx];
        int x = v & 127, y = (v >> 7) & 127, z = v >> 14;
        ull acc[8];
        #pragma unroll
        for (int k = 0; k < 8; k++) acc[k] = 0ull;
        #pragma unroll 1
        for (int dz = 0; dz < 3; dz++){
            int zz = z + dz - 1; if ((unsigned)zz >= 128u) continue;
            #pragma unroll 1
            for (int dy = 0; dy < 3; dy++){
                int yy = y + dy - 1; if ((unsigned)yy >= 128u) continue;
                #pragma unroll 1
                for (int dx = 0; dx < 3; dx++){
                    int xx = x + dx - 1; if ((unsigned)xx >= 128u) continue;
                    int n = (zz << 14) | (yy << 7) | xx;
                    if (!m0[n]) continue;
                    int t = (dz*3 + dy)*3 + dx;
                    const float* wt = ws + t*48;
                    #pragma unroll
                    for (int i = 0; i < 3; i++){
                        ull a = pack2(xf[(size_t)i*DHW0 + n]);
                        const ulonglong2* wp = (const ulonglong2*)(wt + i*16);
                        #pragma unroll
                        for (int j = 0; j < 4; j++){
                            ulonglong2 wv = wp[j];
                            ffma2(acc[2*j],   a, wv.x);
                            ffma2(acc[2*j+1], a, wv.y);
                        }
                    }
                }
            }
        }
        float* dst = g_h0 + (size_t)v*16;
        float r[16];
        #pragma unroll
        for (int k = 0; k < 8; k++){
            float2 p = unpack2(acc[k]);
            r[2*k]   = fmaxf(fmaf(p.x, scale[2*k],   shift[2*k]),   0.f);
            r[2*k+1] = fmaxf(fmaf(p.y, scale[2*k+1], shift[2*k+1]), 0.f);
        }
        #pragma unroll
        for (int m = 0; m < 4; m++)
            ((float4*)dst)[m] = make_float4(r[4*m], r[4*m+1], r[4*m+2], r[4*m+3]);
    }
}

// ============================================================
// conv0b: 16 -> 16 @128^3, sparse
// ============================================================
__global__ void conv0b_kernel(const int* __restrict__ m0, const float* __restrict__ w,
                              const float* __restrict__ scale, const float* __restrict__ shift){
    extern __shared__ float ws[];                 // [27][16][16]
    for (int e = threadIdx.x; e < 27*16*16; e += blockDim.x){
        int o = e & 15, i = (e >> 4) & 15, t = e >> 8;
        ws[e] = w[(o*16 + i)*27 + t];
    }
    __syncthreads();
    int cnt = g_cnt;
    for (int idx = blockIdx.x*blockDim.x + threadIdx.x; idx < cnt;
         idx += gridDim.x*blockDim.x){
        int v = g_active[idx];
        int x = v & 127, y = (v >> 7) & 127, z = v >> 14;
        ull acc[8];
        #pragma unroll
        for (int k = 0; k < 8; k++) acc[k] = 0ull;
        #pragma unroll 1
        for (int dz = 0; dz < 3; dz++){
            int zz = z + dz - 1; if ((unsigned)zz >= 128u) continue;
            #pragma unroll 1
            for (int dy = 0; dy < 3; dy++){
                int yy = y + dy - 1; if ((unsigned)yy >= 128u) continue;
                #pragma unroll 1
                for (int dx = 0; dx < 3; dx++){
                    int xx = x + dx - 1; if ((unsigned)xx >= 128u) continue;
                    int n = (zz << 14) | (yy << 7) | xx;
                    if (!m0[n]) continue;
                    int t = (dz*3 + dy)*3 + dx;
                    const float*  wt = ws + t*256;
                    const float4* ip = (const float4*)(g_h0 + (size_t)n*16);
                    #pragma unroll
                    for (int ig = 0; ig < 4; ig++){
                        float4 xv = ip[ig];
                        float comp[4] = {xv.x, xv.y, xv.z, xv.w};
                        #pragma unroll
                        for (int s = 0; s < 4; s++){
                            ull a = pack2(comp[s]);
                            const ulonglong2* wp = (const ulonglong2*)(wt + (ig*4 + s)*16);
                            #pragma unroll
                            for (int j = 0; j < 4; j++){
                                ulonglong2 wv = wp[j];
                                ffma2(acc[2*j],   a, wv.x);
                                ffma2(acc[2*j+1], a, wv.y);
                            }
                        }
                    }
                }
            }
        }
        float* dst = g_h1 + (size_t)v*16;
        float r[16];
        #pragma unroll
        for (int k = 0; k < 8; k++){
            float2 p = unpack2(acc[k]);
            r[2*k]   = fmaxf(fmaf(p.x, scale[2*k],   shift[2*k]),   0.f);
            r[2*k+1] = fmaxf(fmaf(p.y, scale[2*k+1], shift[2*k+1]), 0.f);
        }
        #pragma unroll
        for (int m = 0; m < 4; m++)
            ((float4*)dst)[m] = make_float4(r[4*m], r[4*m+1], r[4*m+2], r[4*m+3]);
    }
}

// ============================================================
// convd0: 16 -> 32, stride 2, output @64^3 masked by m1; taps check m0
// (must keep tap check: g_h1 is garbage at inactive voxels)
// ============================================================
__global__ void convd0_kernel(const int* __restrict__ m0, const float* __restrict__ w,
                              const float* __restrict__ scale, const float* __restrict__ shift){
    extern __shared__ float ws[];                 // [27][16][32]
    for (int e = threadIdx.x; e < 27*16*32; e += blockDim.x){
        int o = e & 31, i = (e >> 5) & 15, t = e >> 9;
        ws[e] = w[(o*16 + i)*27 + t];
    }
    __syncthreads();
    int v = blockIdx.x*blockDim.x + threadIdx.x;
    if (v >= DHW1) return;
    int x = v & 63, y = (v >> 6) & 63, z = v >> 12;
    float* dst = g_g0 + (size_t)v*32;
    if (!g_m1[v]){
        #pragma unroll
        for (int m = 0; m < 8; m++) ((float4*)dst)[m] = make_float4(0.f,0.f,0.f,0.f);
        return;
    }
    ull acc[16];
    #pragma unroll
    for (int k = 0; k < 16; k++) acc[k] = 0ull;
    #pragma unroll 1
    for (int dz = 0; dz < 3; dz++){
        int iz = 2*z + dz - 1; if ((unsigned)iz >= 128u) continue;
        #pragma unroll 1
        for (int dy = 0; dy < 3; dy++){
            int iy = 2*y + dy - 1; if ((unsigned)iy >= 128u) continue;
            #pragma unroll 1
            for (int dx = 0; dx < 3; dx++){
                int ix = 2*x + dx - 1; if ((unsigned)ix >= 128u) continue;
                int n = (iz << 14) | (iy << 7) | ix;
                if (!m0[n]) continue;
                int t = (dz*3 + dy)*3 + dx;
                const float*  wt = ws + t*512;
                const float4* ip = (const float4*)(g_h1 + (size_t)n*16);
                #pragma unroll
                for (int ig = 0; ig < 4; ig++){
                    float4 xv = ip[ig];
                    float comp[4] = {xv.x, xv.y, xv.z, xv.w};
                    #pragma unroll
                    for (int s = 0; s < 4; s++){
                        ull a = pack2(comp[s]);
                        const ulonglong2* wp = (const ulonglong2*)(wt + (ig*4 + s)*32);
                        #pragma unroll
                        for (int j = 0; j < 8; j++){
                            ulonglong2 wv = wp[j];
                            ffma2(acc[2*j],   a, wv.x);
                            ffma2(acc[2*j+1], a, wv.y);
                        }
                    }
                }
            }
        }
    }
    float r[32];
    #pragma unroll
    for (int k = 0; k < 16; k++){
        float2 p = unpack2(acc[k]);
        r[2*k]   = fmaxf(fmaf(p.x, scale[2*k],   shift[2*k]),   0.f);
        r[2*k+1] = fmaxf(fmaf(p.y, scale[2*k+1], shift[2*k+1]), 0.f);
    }
    #pragma unroll
    for (int m = 0; m < 8; m++)
        ((float4*)dst)[m] = make_float4(r[4*m], r[4*m+1], r[4*m+2], r[4*m+3]);
}

// ============================================================
// conv1: 32 -> 32 @64^3 (phase 0: g0->g1, phase 1: g1->g_h0(reused))
// DENSE taps — inactive neighbors hold exact zeros, so no mask gate,
// no divergence, straight-line FFMA2.
// ============================================================
__global__ void conv1_kernel(int phase, const float* __restrict__ w,
                             const float* __restrict__ scale, const float* __restrict__ shift){
    extern __shared__ float ws[];                 // [27][32][32]
    for (int e = threadIdx.x; e < 27*32*32; e += blockDim.x){
        int o = e & 31, i = (e >> 5) & 31, t = e >> 10;
        ws[e] = w[(o*32 + i)*27 + t];
    }
    __syncthreads();
    const float* in   = phase ? g_g1 : g_g0;
    float*       outb = phase ? g_h0 : g_g1;
    int v = blockIdx.x*blockDim.x + threadIdx.x;
    if (v >= DHW1) return;
    int x = v & 63, y = (v >> 6) & 63, z = v >> 12;
    float* dst = outb + (size_t)v*32;
    if (!g_m1[v]){
        #pragma unroll
        for (int m = 0; m < 8; m++) ((float4*)dst)[m] = make_float4(0.f,0.f,0.f,0.f);
        return;
    }
    ull acc[16];
    #pragma unroll
    for (int k = 0; k < 16; k++) acc[k] = 0ull;
    #pragma unroll 1
    for (int dz = 0; dz < 3; dz++){
        int zz = z + dz - 1; if ((unsigned)zz >= 64u) continue;
        #pragma unroll 1
        for (int dy = 0; dy < 3; dy++){
            int yy = y + dy - 1; if ((unsigned)yy >= 64u) continue;
            #pragma unroll 1
            for (int dx = 0; dx < 3; dx++){
                int xx = x + dx - 1; if ((unsigned)xx >= 64u) continue;
                int n = (zz << 12) | (yy << 6) | xx;
                int t = (dz*3 + dy)*3 + dx;
                const float*  wt = ws + t*1024;
                const float4* ip = (const float4*)(in + (size_t)n*32);
                #pragma unroll
                for (int ig = 0; ig < 8; ig++){
                    float4 xv = ip[ig];
                    float comp[4] = {xv.x, xv.y, xv.z, xv.w};
                    #pragma unroll
                    for (int s = 0; s < 4; s++){
                        ull a = pack2(comp[s]);
                        const ulonglong2* wp = (const ulonglong2*)(wt + (ig*4 + s)*32);
                        #pragma unroll
                        for (int j = 0; j < 8; j++){
                            ulonglong2 wv = wp[j];
                            ffma2(acc[2*j],   a, wv.x);
                            ffma2(acc[2*j+1], a, wv.y);
                        }
                    }
                }
            }
        }
    }
    float r[32];
    #pragma unroll
    for (int k = 0; k < 16; k++){
        float2 p = unpack2(acc[k]);
        r[2*k]   = fmaxf(fmaf(p.x, scale[2*k],   shift[2*k]),   0.f);
        r[2*k+1] = fmaxf(fmaf(p.y, scale[2*k+1], shift[2*k+1]), 0.f);
    }
    #pragma unroll
    for (int m = 0; m < 8; m++)
        ((float4*)dst)[m] = make_float4(r[4*m], r[4*m+1], r[4*m+2], r[4*m+3]);
}

// ============================================================
// Trilinear sampling of final volume (in g_h0), out[p][c] fp32
// ============================================================
__global__ void sample_kernel(const float* __restrict__ coords, float* __restrict__ out){
    int p = blockIdx.x*blockDim.x + threadIdx.x;
    if (p >= 65536) return;
    float cx = coords[3*p], cy = coords[3*p + 1], cz = coords[3*p + 2];
    float fx = (cx + 1.f)*0.5f*63.f;
    float fy = (cy + 1.f)*0.5f*63.f;
    float fz = (cz + 1.f)*0.5f*63.f;
    float x0f = floorf(fx), y0f = floorf(fy), z0f = floorf(fz);
    int x0 = (int)x0f, y0 = (int)y0f, z0 = (int)z0f;
    float tx = fx - x0f, ty = fy - y0f, tz = fz - z0f;
    ull acc[16];
    #pragma unroll
    for (int k = 0; k < 16; k++) acc[k] = 0ull;
    #pragma unroll
    for (int dz = 0; dz < 2; dz++){
        #pragma unroll
        for (int dy = 0; dy < 2; dy++){
            #pragma unroll
            for (int dx = 0; dx < 2; dx++){
                int xi = x0 + dx, yi = y0 + dy, zi = z0 + dz;
                if ((unsigned)xi >= 64u || (unsigned)yi >= 64u || (unsigned)zi >= 64u)
                    continue;                      // ref zeroes weight out of bounds
                float wgt = (dx ? tx : 1.f - tx) * (dy ? ty : 1.f - ty) * (dz ? tz : 1.f - tz);
                ull a = pack2(wgt);
                const ulonglong2* vp =
                    (const ulonglong2*)(g_h0 + (size_t)(((zi*64 + yi)*64) + xi)*32);
                #pragma unroll
                for (int j = 0; j < 8; j++){
                    ulonglong2 q = vp[j];
                    ffma2(acc[2*j],   a, q.x);
                    ffma2(acc[2*j+1], a, q.y);
                }
            }
        }
    }
    float r[32];
    #pragma unroll
    for (int k = 0; k < 16; k++){
        float2 pv = unpack2(acc[k]);
        r[2*k] = pv.x; r[2*k+1] = pv.y;
    }
    float4* op = (float4*)(out + (size_t)p*32);
    #pragma unroll
    for (int m = 0; m < 8; m++)
        op[m] = make_float4(r[4*m], r[4*m+1], r[4*m+2], r[4*m+3]);
}

// ============================================================
extern "C" void kernel_launch(void* const* d_in, const int* in_sizes, int n_in,
                              void* d_out, int out_size){
    const float* xf     = (const float*)d_in[0];
    const int*   m0     = (const int*)  d_in[1];
    const float* coords = (const float*)d_in[2];
    const float* w0a = (const float*)d_in[3];
    const float* s0a = (const float*)d_in[4];
    const float* b0a = (const float*)d_in[5];
    const float* w0b = (const float*)d_in[6];
    const float* s0b = (const float*)d_in[7];
    const float* b0b = (const float*)d_in[8];
    const float* wd0 = (const float*)d_in[9];
    const float* sd0 = (const float*)d_in[10];
    const float* bd0 = (const float*)d_in[11];
    const float* w1a = (const float*)d_in[12];
    const float* s1a = (const float*)d_in[13];
    const float* b1a = (const float*)d_in[14];
    const float* w1b = (const float*)d_in[15];
    const float* s1b = (const float*)d_in[16];
    const float* b1b = (const float*)d_in[17];
    float* out = (float*)d_out;

    // opt-in shared memory > 48KB (host-side, idempotent, capture-safe;
    // called unconditionally — no static guards per harness rules)
    cudaFuncSetAttribute(convd0_kernel, cudaFuncAttributeMaxDynamicSharedMemorySize, 27*16*32*4);
    cudaFuncSetAttribute(conv1_kernel,  cudaFuncAttributeMaxDynamicSharedMemorySize, 27*32*32*4);

    count_kernel  <<<8192, 256>>>(m0);
    scan_kernel   <<<1, 1024>>>();
    scatter_kernel<<<8192, 256>>>(m0);
    m1_kernel     <<<1024, 256>>>(m0);

    conv0a_kernel<<<2048, 128, 27*3*16*4>>>(xf, m0, w0a, s0a, b0a);
    conv0b_kernel<<<2048, 128, 27*16*16*4>>>(m0, w0b, s0b, b0b);
    convd0_kernel<<<1024, 256, 27*16*32*4>>>(m0, wd0, sd0, bd0);
    conv1_kernel <<<1024, 256, 27*32*32*4>>>(0, w1a, s1a, b1a);
    conv1_kernel <<<1024, 256, 27*32*32*4>>>(1, w1b, s1b, b1b);
    sample_kernel<<<256, 256>>>(coords, out);
}

// round 5
// speedup vs baseline: 1.5458x; 1.5458x over previous
#include <cuda_runtime.h>

typedef unsigned long long ull;

#define DHW0 (128*128*128)
#define DHW1 (64*64*64)

// Scratch (device globals: allocation-free rule).
__device__ float g_h0[(size_t)DHW0*16];   // conv0a out; later reused: conv1b planar out
__device__ float g_h1[(size_t)DHW0*16];   // conv0b out; later reused: conv1b interleaved out
__device__ float g_g0[(size_t)DHW1*32];   // convd0 out (planar [c][v])
__device__ float g_g1[(size_t)DHW1*32];   // conv1a out (planar [c][v])
__device__ int   g_m1[DHW1];
__device__ int   g_active[DHW0];
__device__ int   g_blockcnt[8192];
__device__ int   g_blockoff[8192];
__device__ int   g_cnt;

// ---- packed f32x2 helpers ----
__device__ __forceinline__ ull pack2(float a){
    ull r; asm("mov.b64 %0, {%1, %1};" : "=l"(r) : "f"(a)); return r;
}
__device__ __forceinline__ void ffma2(ull& c, ull a, ull b){
    asm("fma.rn.f32x2 %0, %1, %2, %0;" : "+l"(c) : "l"(a), "l"(b));
}
__device__ __forceinline__ float2 unpack2(ull v){
    float2 f; asm("mov.b64 {%0, %1}, %2;" : "=f"(f.x), "=f"(f.y) : "l"(v)); return f;
}

// ============================================================
// Active-voxel compaction (deterministic)
// ============================================================
__global__ void count_kernel(const int* __restrict__ m0){
    int v = blockIdx.x*256 + threadIdx.x;
    int act = m0[v] ? 1 : 0;
    int c = __syncthreads_count(act);
    if (threadIdx.x == 0) g_blockcnt[blockIdx.x] = c;
}

__global__ void scan_kernel(){
    __shared__ int ssum[1024];
    int tid = threadIdx.x;
    int local[8]; int s = 0;
    #pragma unroll
    for (int k = 0; k < 8; k++){ local[k] = s; s += g_blockcnt[tid*8 + k]; }
    ssum[tid] = s; __syncthreads();
    for (int off = 1; off < 1024; off <<= 1){
        int val = (tid >= off) ? ssum[tid - off] : 0;
        __syncthreads();
        ssum[tid] += val;
        __syncthreads();
    }
    int base = (tid == 0) ? 0 : ssum[tid - 1];
    #pragma unroll
    for (int k = 0; k < 8; k++) g_blockoff[tid*8 + k] = base + local[k];
    if (tid == 1023) g_cnt = ssum[1023];
}

__global__ void scatter_kernel(const int* __restrict__ m0){
    __shared__ int warpoff[8];
    int v = blockIdx.x*256 + threadIdx.x;
    int act = m0[v] ? 1 : 0;
    unsigned b = __ballot_sync(0xffffffffu, act);
    int lane = threadIdx.x & 31, wid = threadIdx.x >> 5;
    if (lane == 0) warpoff[wid] = __popc(b);
    __syncthreads();
    if (threadIdx.x == 0){
        int s = 0;
        #pragma unroll
        for (int k = 0; k < 8; k++){ int t = warpoff[k]; warpoff[k] = s; s += t; }
    }
    __syncthreads();
    if (act){
        int rank = warpoff[wid] + __popc(b & ((1u << lane) - 1u));
        g_active[g_blockoff[blockIdx.x] + rank] = v;
    }
}

// ============================================================
// m1 = maxpool3d(m0, 3, stride 2, pad 1)
// ============================================================
__global__ void m1_kernel(const int* __restrict__ m0){
    int v = blockIdx.x*256 + threadIdx.x;
    if (v >= DHW1) return;
    int x = v & 63, y = (v >> 6) & 63, z = v >> 12;
    int mv = 0;
    for (int dz = 0; dz < 3; dz++){
        int iz = 2*z + dz - 1; if ((unsigned)iz >= 128u) continue;
        for (int dy = 0; dy < 3; dy++){
            int iy = 2*y + dy - 1; if ((unsigned)iy >= 128u) continue;
            for (int dx = 0; dx < 3; dx++){
                int ix = 2*x + dx - 1; if ((unsigned)ix >= 128u) continue;
                mv |= m0[(iz << 14) | (iy << 7) | ix];
            }
        }
    }
    g_m1[v] = mv;
}

// ============================================================
// conv0a: 3 -> 16 @128^3, sparse
// ============================================================
__global__ void conv0a_kernel(const float* __restrict__ xf, const int* __restrict__ m0,
                              const float* __restrict__ w, const float* __restrict__ scale,
                              const float* __restrict__ shift){
    extern __shared__ float ws[];                 // [27][3][16]
    for (int e = threadIdx.x; e < 27*3*16; e += blockDim.x){
        int o = e & 15, i = (e >> 4) % 3, t = e / 48;
        ws[e] = w[(o*3 + i)*27 + t];
    }
    __syncthreads();
    int cnt = g_cnt;
    for (int idx = blockIdx.x*blockDim.x + threadIdx.x; idx < cnt;
         idx += gridDim.x*blockDim.x){
        int v = g_active[idx];
        int x = v & 127, y = (v >> 7) & 127, z = v >> 14;
        ull acc[8];
        #pragma unroll
        for (int k = 0; k < 8; k++) acc[k] = 0ull;
        #pragma unroll 1
        for (int dz = 0; dz < 3; dz++){
            int zz = z + dz - 1; if ((unsigned)zz >= 128u) continue;
            #pragma unroll 1
            for (int dy = 0; dy < 3; dy++){
                int yy = y + dy - 1; if ((unsigned)yy >= 128u) continue;
                #pragma unroll 1
                for (int dx = 0; dx < 3; dx++){
                    int xx = x + dx - 1; if ((unsigned)xx >= 128u) continue;
                    int n = (zz << 14) | (yy << 7) | xx;
                    if (!m0[n]) continue;
                    int t = (dz*3 + dy)*3 + dx;
                    const float* wt = ws + t*48;
                    #pragma unroll
                    for (int i = 0; i < 3; i++){
                        ull a = pack2(xf[(size_t)i*DHW0 + n]);
                        const ulonglong2* wp = (const ulonglong2*)(wt + i*16);
                        #pragma unroll
                        for (int j = 0; j < 4; j++){
                            ulonglong2 wv = wp[j];
                            ffma2(acc[2*j],   a, wv.x);
                            ffma2(acc[2*j+1], a, wv.y);
                        }
                    }
                }
            }
        }
        float* dst = g_h0 + (size_t)v*16;
        float r[16];
        #pragma unroll
        for (int k = 0; k < 8; k++){
            float2 p = unpack2(acc[k]);
            r[2*k]   = fmaxf(fmaf(p.x, scale[2*k],   shift[2*k]),   0.f);
            r[2*k+1] = fmaxf(fmaf(p.y, scale[2*k+1], shift[2*k+1]), 0.f);
        }
        #pragma unroll
        for (int m = 0; m < 4; m++)
            ((float4*)dst)[m] = make_float4(r[4*m], r[4*m+1], r[4*m+2], r[4*m+3]);
    }
}

// ============================================================
// conv0b: 16 -> 16 @128^3, sparse
// ============================================================
__global__ void conv0b_kernel(const int* __restrict__ m0, const float* __restrict__ w,
                              const float* __restrict__ scale, const float* __restrict__ shift){
    extern __shared__ float ws[];                 // [27][16][16]
    for (int e = threadIdx.x; e < 27*16*16; e += blockDim.x){
        int o = e & 15, i = (e >> 4) & 15, t = e >> 8;
        ws[e] = w[(o*16 + i)*27 + t];
    }
    __syncthreads();
    int cnt = g_cnt;
    for (int idx = blockIdx.x*blockDim.x + threadIdx.x; idx < cnt;
         idx += gridDim.x*blockDim.x){
        int v = g_active[idx];
        int x = v & 127, y = (v >> 7) & 127, z = v >> 14;
        ull acc[8];
        #pragma unroll
        for (int k = 0; k < 8; k++) acc[k] = 0ull;
        #pragma unroll 1
        for (int dz = 0; dz < 3; dz++){
            int zz = z + dz - 1; if ((unsigned)zz >= 128u) continue;
            #pragma unroll 1
            for (int dy = 0; dy < 3; dy++){
                int yy = y + dy - 1; if ((unsigned)yy >= 128u) continue;
                #pragma unroll 1
                for (int dx = 0; dx < 3; dx++){
                    int xx = x + dx - 1; if ((unsigned)xx >= 128u) continue;
                    int n = (zz << 14) | (yy << 7) | xx;
                    if (!m0[n]) continue;
                    int t = (dz*3 + dy)*3 + dx;
                    const float*  wt = ws + t*256;
                    const float4* ip = (const float4*)(g_h0 + (size_t)n*16);
                    #pragma unroll
                    for (int ig = 0; ig < 4; ig++){
                        float4 xv = ip[ig];
                        float comp[4] = {xv.x, xv.y, xv.z, xv.w};
                        #pragma unroll
                        for (int s = 0; s < 4; s++){
                            ull a = pack2(comp[s]);
                            const ulonglong2* wp = (const ulonglong2*)(wt + (ig*4 + s)*16);
                            #pragma unroll
                            for (int j = 0; j < 4; j++){
                                ulonglong2 wv = wp[j];
                                ffma2(acc[2*j],   a, wv.x);
                                ffma2(acc[2*j+1], a, wv.y);
                            }
                        }
                    }
                }
            }
        }
        float* dst = g_h1 + (size_t)v*16;
        float r[16];
        #pragma unroll
        for (int k = 0; k < 8; k++){
            float2 p = unpack2(acc[k]);
            r[2*k]   = fmaxf(fmaf(p.x, scale[2*k],   shift[2*k]),   0.f);
            r[2*k+1] = fmaxf(fmaf(p.y, scale[2*k+1], shift[2*k+1]), 0.f);
        }
        #pragma unroll
        for (int m = 0; m < 4; m++)
            ((float4*)dst)[m] = make_float4(r[4*m], r[4*m+1], r[4*m+2], r[4*m+3]);
    }
}

// ============================================================
// convd0: 16 -> 32, stride 2 -> PLANAR output g_g0[c][v]
// ============================================================
__global__ void convd0_kernel(const int* __restrict__ m0, const float* __restrict__ w,
                              const float* __restrict__ scale, const float* __restrict__ shift){
    extern __shared__ float ws[];                 // [27][16][32]
    for (int e = threadIdx.x; e < 27*16*32; e += blockDim.x){
        int o = e & 31, i = (e >> 5) & 15, t = e >> 9;
        ws[e] = w[(o*16 + i)*27 + t];
    }
    __syncthreads();
    int v = blockIdx.x*blockDim.x + threadIdx.x;
    if (v >= DHW1) return;
    int x = v & 63, y = (v >> 6) & 63, z = v >> 12;
    if (!g_m1[v]){
        #pragma unroll
        for (int c = 0; c < 32; c++) g_g0[(size_t)c*DHW1 + v] = 0.f;
        return;
    }
    ull acc[16];
    #pragma unroll
    for (int k = 0; k < 16; k++) acc[k] = 0ull;
    #pragma unroll 1
    for (int dz = 0; dz < 3; dz++){
        int iz = 2*z + dz - 1; if ((unsigned)iz >= 128u) continue;
        #pragma unroll 1
        for (int dy = 0; dy < 3; dy++){
            int iy = 2*y + dy - 1; if ((unsigned)iy >= 128u) continue;
            #pragma unroll 1
            for (int dx = 0; dx < 3; dx++){
                int ix = 2*x + dx - 1; if ((unsigned)ix >= 128u) continue;
                int n = (iz << 14) | (iy << 7) | ix;
                if (!m0[n]) continue;
                int t = (dz*3 + dy)*3 + dx;
                const float*  wt = ws + t*512;
                const float4* ip = (const float4*)(g_h1 + (size_t)n*16);
                #pragma unroll
                for (int ig = 0; ig < 4; ig++){
                    float4 xv = ip[ig];
                    float comp[4] = {xv.x, xv.y, xv.z, xv.w};
                    #pragma unroll
                    for (int s = 0; s < 4; s++){
                        ull a = pack2(comp[s]);
                        const ulonglong2* wp = (const ulonglong2*)(wt + (ig*4 + s)*32);
                        #pragma unroll
                        for (int j = 0; j < 8; j++){
                            ulonglong2 wv = wp[j];
                            ffma2(acc[2*j],   a, wv.x);
                            ffma2(acc[2*j+1], a, wv.y);
                        }
                    }
                }
            }
        }
    }
    #pragma unroll
    for (int k = 0; k < 16; k++){
        float2 p = unpack2(acc[k]);
        g_g0[(size_t)(2*k  )*DHW1 + v] = fmaxf(fmaf(p.x, scale[2*k],   shift[2*k]),   0.f);
        g_g0[(size_t)(2*k+1)*DHW1 + v] = fmaxf(fmaf(p.y, scale[2*k+1], shift[2*k+1]), 0.f);
    }
}

// ============================================================
// conv1 v2: 32 -> 32 @64^3, planar in/out, smem-tiled, x-strip per thread.
// Block: (z, 4 y-rows). Threads 256: coutgrp = tid&3 (8 couts),
// xseg = (tid>>2)&15 (4 x), yloc = tid>>6 (0..3).
// Smem: input tile [8ci][3zz][6yy][68] + weights [27][8][32].
// phase1 additionally writes interleaved copy for the sampler.
// ============================================================
#define C1_IN_STRIDE 68
#define C1_IN_ELEMS  (8*3*6*C1_IN_STRIDE)     // 9792
#define C1_W_ELEMS   (27*8*32)                // 6912
#define C1_SMEM_BYTES ((C1_IN_ELEMS + C1_W_ELEMS)*4)

__global__ __launch_bounds__(256) void conv1_kernel(
        const float* __restrict__ in, float* __restrict__ outp,
        float* __restrict__ outi, int write_inter,
        const float* __restrict__ w,
        const float* __restrict__ scale, const float* __restrict__ shift){
    extern __shared__ float sm[];
    float* sm_in = sm;
    float* sm_w  = sm + C1_IN_ELEMS;

    int tid = threadIdx.x;
    int cg   = tid & 3;            // cout group: couts 8*cg..8*cg+7
    int xseg = (tid >> 2) & 15;    // x strip: 4*xseg..+3
    int yloc = tid >> 6;           // 0..3
    int z  = blockIdx.x >> 4;
    int y0 = (blockIdx.x & 15) << 2;
    int x0 = xseg << 2;
    int yy_out = y0 + yloc;

    ull acc[4][4];                 // [coutpair][xloc] ; pair = (2cp, 2cp+1) within group
    #pragma unroll
    for (int a = 0; a < 4; a++)
        #pragma unroll
        for (int b = 0; b < 4; b++) acc[a][b] = 0ull;

    for (int cb = 0; cb < 32; cb += 8){
        // ---- stage inputs: ci in [cb, cb+8), zz in z-1..z+1, yy in y0-1..y0+4, x in -1..64
        for (int e = tid; e < C1_IN_ELEMS; e += 256){
            int xi  = e % C1_IN_STRIDE;
            int rst = e / C1_IN_STRIDE;
            int yy  = rst % 6; rst /= 6;
            int zz  = rst % 3;
            int ci  = rst / 3;
            int gx = xi - 1, gy = y0 + yy - 1, gz = z + zz - 1;
            float val = 0.f;
            if ((unsigned)gx < 64u && (unsigned)gy < 64u && (unsigned)gz < 64u && xi < 66)
                val = in[(size_t)(cb + ci)*DHW1 + (gz << 12) + (gy << 6) + gx];
            sm_in[e] = val;
        }
        // ---- stage weights: ws[t][ci][co]
        for (int e = tid; e < C1_W_ELEMS; e += 256){
            int co = e & 31, ci = (e >> 5) & 7, t = e >> 8;
            sm_w[e] = w[(co*32 + cb + ci)*27 + t];
        }
        __syncthreads();

        #pragma unroll 1
        for (int ci = 0; ci < 8; ci++){
            #pragma unroll 1
            for (int dz = 0; dz < 3; dz++){
                #pragma unroll 1
                for (int dy = 0; dy < 3; dy++){
                    const float* row = sm_in + ((ci*3 + dz)*6 + (yloc + dy))*C1_IN_STRIDE + x0;
                    float i0 = row[0], i1 = row[1], i2 = row[2],
                          i3 = row[3], i4 = row[4], i5 = row[5];
                    ull ap[6];
                    ap[0] = pack2(i0); ap[1] = pack2(i1); ap[2] = pack2(i2);
                    ap[3] = pack2(i3); ap[4] = pack2(i4); ap[5] = pack2(i5);
                    const float* wt = sm_w + ((dz*3 + dy)*3)*256 + ci*32 + cg*8;
                    #pragma unroll
                    for (int dx = 0; dx < 3; dx++){
                        const ulonglong2* wp = (const ulonglong2*)(wt + dx*256);
                        ulonglong2 w01 = wp[0];
                        ulonglong2 w23 = wp[1];
                        #pragma unroll
                        for (int xl = 0; xl < 4; xl++){
                            ull a = ap[xl + dx];
                            ffma2(acc[0][xl], a, w01.x);
                            ffma2(acc[1][xl], a, w01.y);
                            ffma2(acc[2][xl], a, w23.x);
                            ffma2(acc[3][xl], a, w23.y);
                        }
                    }
                }
            }
        }
        __syncthreads();
    }

    // ---- epilogue: BN + ReLU + m1 mask, planar store (+ optional interleaved)
    int vbase = (z << 12) + (yy_out << 6) + x0;
    float mv[4];
    #pragma unroll
    for (int xl = 0; xl < 4; xl++) mv[xl] = g_m1[vbase + xl] ? 1.f : 0.f;
    #pragma unroll
    for (int cp = 0; cp < 4; cp++){
        int c0 = cg*8 + 2*cp, c1 = c0 + 1;
        float s0 = scale[c0], s1 = scale[c1], h0 = shift[c0], h1 = shift[c1];
        #pragma unroll
        for (int xl = 0; xl < 4; xl++){
            float2 p = unpack2(acc[cp][xl]);
            float r0 = fmaxf(fmaf(p.x, s0, h0), 0.f) * mv[xl];
            float r1 = fmaxf(fmaf(p.y, s1, h1), 0.f) * mv[xl];
            outp[(size_t)c0*DHW1 + vbase + xl] = r0;
            outp[(size_t)c1*DHW1 + vbase + xl] = r1;
            if (write_inter)
                *(float2*)(outi + (size_t)(vbase + xl)*32 + c0) = make_float2(r0, r1);
        }
    }
}

// ============================================================
// Trilinear sampling of final volume (interleaved copy in g_h1)
// ============================================================
__global__ void sample_kernel(const float* __restrict__ coords, float* __restrict__ out){
    int p = blockIdx.x*blockDim.x + threadIdx.x;
    if (p >= 65536) return;
    float cx = coords[3*p], cy = coords[3*p + 1], cz = coords[3*p + 2];
    float fx = (cx + 1.f)*0.5f*63.f;
    float fy = (cy + 1.f)*0.5f*63.f;
    float fz = (cz + 1.f)*0.5f*63.f;
    float x0f = floorf(fx), y0f = floorf(fy), z0f = floorf(fz);
    int x0 = (int)x0f, y0 = (int)y0f, z0 = (int)z0f;
    float tx = fx - x0f, ty = fy - y0f, tz = fz - z0f;
    ull acc[16];
    #pragma unroll
    for (int k = 0; k < 16; k++) acc[k] = 0ull;
    #pragma unroll
    for (int dz = 0; dz < 2; dz++){
        #pragma unroll
        for (int dy = 0; dy < 2; dy++){
            #pragma unroll
            for (int dx = 0; dx < 2; dx++){
                int xi = x0 + dx, yi = y0 + dy, zi = z0 + dz;
                if ((unsigned)xi >= 64u || (unsigned)yi >= 64u || (unsigned)zi >= 64u)
                    continue;
                float wgt = (dx ? tx : 1.f - tx) * (dy ? ty : 1.f - ty) * (dz ? tz : 1.f - tz);
                ull a = pack2(wgt);
                const ulonglong2* vp =
                    (const ulonglong2*)(g_h1 + (size_t)(((zi*64 + yi)*64) + xi)*32);
                #pragma unroll
                for (int j = 0; j < 8; j++){
                    ulonglong2 q = vp[j];
                    ffma2(acc[2*j],   a, q.x);
                    ffma2(acc[2*j+1], a, q.y);
                }
            }
        }
    }
    float r[32];
    #pragma unroll
    for (int k = 0; k < 16; k++){
        float2 pv = unpack2(acc[k]);
        r[2*k] = pv.x; r[2*k+1] = pv.y;
    }
    float4* op = (float4*)(out + (size_t)p*32);
    #pragma unroll
    for (int m = 0; m < 8; m++)
        op[m] = make_float4(r[4*m], r[4*m+1], r[4*m+2], r[4*m+3]);
}

// ============================================================
extern "C" void kernel_launch(void* const* d_in, const int* in_sizes, int n_in,
                              void* d_out, int out_size){
    const float* xf     = (const float*)d_in[0];
    const int*   m0     = (const int*)  d_in[1];
    const float* coords = (const float*)d_in[2];
    const float* w0a = (const float*)d_in[3];
    const float* s0a = (const float*)d_in[4];
    const float* b0a = (const float*)d_in[5];
    const float* w0b = (const float*)d_in[6];
    const float* s0b = (const float*)d_in[7];
    const float* b0b = (const float*)d_in[8];
    const float* wd0 = (const float*)d_in[9];
    const float* sd0 = (const float*)d_in[10];
    const float* bd0 = (const float*)d_in[11];
    const float* w1a = (const float*)d_in[12];
    const float* s1a = (const float*)d_in[13];
    const float* b1a = (const float*)d_in[14];
    const float* w1b = (const float*)d_in[15];
    const float* s1b = (const float*)d_in[16];
    const float* b1b = (const float*)d_in[17];
    float* out = (float*)d_out;

    // planar buffer device addresses (host-side queries; allocation-free)
    float *p_g0, *p_g1, *p_h0, *p_h1;
    cudaGetSymbolAddress((void**)&p_g0, g_g0);
    cudaGetSymbolAddress((void**)&p_g1, g_g1);
    cudaGetSymbolAddress((void**)&p_h0, g_h0);
    cudaGetSymbolAddress((void**)&p_h1, g_h1);

    cudaFuncSetAttribute(convd0_kernel, cudaFuncAttributeMaxDynamicSharedMemorySize, 27*16*32*4);
    cudaFuncSetAttribute(conv1_kernel,  cudaFuncAttributeMaxDynamicSharedMemorySize, C1_SMEM_BYTES);

    count_kernel  <<<8192, 256>>>(m0);
    scan_kernel   <<<1, 1024>>>();
    scatter_kernel<<<8192, 256>>>(m0);
    m1_kernel     <<<1024, 256>>>(m0);

    conv0a_kernel<<<2048, 128, 27*3*16*4>>>(xf, m0, w0a, s0a, b0a);
    conv0b_kernel<<<2048, 128, 27*16*16*4>>>(m0, w0b, s0b, b0b);
    convd0_kernel<<<1024, 256, 27*16*32*4>>>(m0, wd0, sd0, bd0);
    conv1_kernel <<<1024, 256, C1_SMEM_BYTES>>>(p_g0, p_g1, (float*)0, 0, w1a, s1a, b1a);
    conv1_kernel <<<1024, 256, C1_SMEM_BYTES>>>(p_g1, p_h0, p_h1,      1, w1b, s1b, b1b);
    sample_kernel<<<256, 256>>>(coords, out);
}